// round 6
// baseline (speedup 1.0000x reference)
#include <cuda_runtime.h>
#include <math.h>

#define BB 4
#define CC 8
#define HH 256
#define WW 256
#define INF_D 512
#define JT 16                         // columns per colpass tile

// Static device scratch (no allocations allowed)
__device__ unsigned short g_gin[BB*CC*HH*WW];   // 4 MB: per-class row distance (inside)
__device__ unsigned short g_tr[BB*HH*WW];       // 0.5 MB: packed (t<<10 | r)
__device__ float          g_prob[BB*CC*HH*WW];  // 8 MB: softmax probabilities
__device__ int            g_cnt[BB*CC];         // class presence counts
__device__ float          g_part[BB*CC*(WW/JT)];// 512 block partial sums

// ---------------------------------------------------------------------------
__global__ void k_init() {
    int i = threadIdx.x;
    if (i < BB*CC) g_cnt[i] = 0;
}

// Standalone softmax: one float2 (2 pixels) per thread, 131072 threads.
__global__ void k_softmax(const float* __restrict__ output) {
    const int q   = blockIdx.x * 128 + threadIdx.x;   // 0 .. 131071 (pixel/2)
    const int b   = q >> 15;
    const int hw2 = q & 32767;
    const float2* out2 = (const float2*)output;
    float2* prob2 = (float2*)g_prob;

    float2 lg[CC];
    float mx = -1e30f, my = -1e30f;
    #pragma unroll
    for (int c = 0; c < CC; ++c) {
        lg[c] = out2[(b*CC + c)*32768 + hw2];
        mx = fmaxf(mx, lg[c].x); my = fmaxf(my, lg[c].y);
    }
    float sx = 0.f, sy = 0.f;
    #pragma unroll
    for (int c = 0; c < CC; ++c) {
        lg[c].x = __expf(lg[c].x - mx); sx += lg[c].x;
        lg[c].y = __expf(lg[c].y - my); sy += lg[c].y;
    }
    const float ix = 1.f/sx, iy = 1.f/sy;
    #pragma unroll
    for (int c = 0; c < CC; ++c)
        prob2[(b*CC + c)*32768 + hw2] = make_float2(lg[c].x*ix, lg[c].y*iy);
}

// Nearest set bit distance in a 256-bit mask (8 words), bits optionally
// inverted by xor with `inv`. Returns 0 if bit j itself is set; INF_D if none.
__device__ __forceinline__ int nearest_bit(const unsigned* wd, unsigned inv, int j) {
    const int wj = j >> 5, bj = j & 31;
    const unsigned cur = wd[wj] ^ inv;
    int dl = INF_D, dr = INF_D;

    unsigned m = cur & (0xffffffffu >> (31 - bj));   // bits [0..bj]
    if (m) {
        dl = bj - (31 - __clz(m));
    } else {
        #pragma unroll
        for (int w = 6; w >= 0; --w) {               // first nonzero word below
            if (w < wj) {
                const unsigned mw = wd[w] ^ inv;
                if (mw) { dl = j - (w*32 + 31 - __clz(mw)); break; }
            }
        }
    }
    m = cur >> bj;                                   // bits [bj..31]
    if (m) {
        dr = __ffs(m) - 1;
    } else {
        #pragma unroll
        for (int w = 1; w <= 7; ++w) {               // first nonzero word above
            if (w > wj) {
                const unsigned mw = wd[w] ^ inv;
                if (mw) { dr = (w*32 + __ffs(mw) - 1) - j; break; }
            }
        }
    }
    int d = dl < dr ? dl : dr;
    return d < INF_D ? d : INF_D;
}

// Row pass: one block per (b, h) row. Bitmask-based nearest-site distances.
__global__ void k_rowpass(const int* __restrict__ target) {
    const int row = blockIdx.x;          // b*HH + h
    const int b   = row / HH;
    const int h   = row % HH;
    const int j   = threadIdx.x;
    const int w   = j >> 5;              // warp id 0..7
    const int ln  = j & 31;

    __shared__ unsigned mask[CC][8];     // 256-bit occupancy per class
    const int t = target[row * WW + j];

    #pragma unroll
    for (int c = 0; c < CC; ++c) {
        const unsigned m = __ballot_sync(0xffffffffu, t == c);
        if (ln == 0) mask[c][w] = m;
    }
    __syncthreads();

    // r: nearest column whose class differs from t  (complement of mask[t])
    const int r = nearest_bit(mask[t], 0xffffffffu, j);
    g_tr[row * WW + j] = (unsigned short)(r | (t << 10));

    // gin[c]: nearest column with class c
    #pragma unroll
    for (int c = 0; c < CC; ++c) {
        const int g = nearest_bit(mask[c], 0u, j);
        g_gin[((b*CC + c)*HH + h)*WW + j] = (unsigned short)g;
    }

    // presence counts: threads 0..7, one class each
    if (j < CC) {
        int cnt = 0;
        #pragma unroll
        for (int k = 0; k < 8; ++k) cnt += __popc(mask[j][k]);
        if (cnt) atomicAdd(&g_cnt[b*CC + j], cnt);
    }
}

// Fused column pass + weighted reduce: one block per (bc, 16-col tile).
// Coalesced tile load, exact early-exit EDT combine, multiply by softmax
// prob, block-reduce to one partial (gated by class presence).
__global__ void k_colpass() {
    const int jt  = blockIdx.x & (WW/JT - 1);   // 0..15
    const int bc  = blockIdx.x / (WW/JT);
    const int b   = bc >> 3;
    const int c   = bc & 7;
    const int j0  = jt * JT;

    __shared__ float s_in[HH][JT];
    __shared__ float s_out[HH][JT];

    const int jj = threadIdx.x & (JT - 1);
    const int k0 = threadIdx.x / JT;            // 0..15

    // Cooperative coalesced load: warp lanes span 2 rows x 16 contiguous cols.
    #pragma unroll
    for (int m = 0; m < HH/16; ++m) {
        const int k = k0 + 16*m;
        const unsigned v = g_tr[(b*HH + k)*WW + j0 + jj];
        const int t = (int)(v >> 10);
        const float gout = (t == c) ? (float)(v & 1023u) : 0.0f;
        const float gin  = (float)g_gin[(bc*HH + k)*WW + j0 + jj];
        s_in[k][jj]  = gin * gin;
        s_out[k][jj] = gout * gout;
    }
    __syncthreads();

    // Each thread: column jj, rows i = k0 + 16*m (16 outputs).
    // Exact early exit: after rejecting distance d, any unexamined k has
    // (i-k)^2 >= d^2, so stop when d^2 >= both running minima.
    float acc = 0.0f;
    for (int m = 0; m < HH/16; ++m) {
        const int i = k0 + 16*m;
        float din2  = s_in[i][jj];
        float dout2 = s_out[i][jj];
        for (int d = 1; d < HH; ++d) {
            const float dd2 = (float)(d * d);
            if (dd2 >= din2 && dd2 >= dout2) break;
            const int lo = i - d, hi = i + d;
            if (lo >= 0) {
                din2  = fminf(din2,  dd2 + s_in[lo][jj]);
                dout2 = fminf(dout2, dd2 + s_out[lo][jj]);
            }
            if (hi < HH) {
                din2  = fminf(din2,  dd2 + s_in[hi][jj]);
                dout2 = fminf(dout2, dd2 + s_out[hi][jj]);
            }
        }
        const float dmap = sqrtf(din2) - sqrtf(dout2);
        acc += dmap * g_prob[(bc*HH + i)*WW + j0 + jj];
    }

    // Block reduce 256 partials -> 1, gate by presence.
    __syncthreads();                     // reuse s_in as reduce scratch
    float* sred = &s_in[0][0];
    sred[threadIdx.x] = acc;
    __syncthreads();
    #pragma unroll
    for (int s = 128; s > 0; s >>= 1) {
        if (threadIdx.x < s) sred[threadIdx.x] += sred[threadIdx.x + s];
        __syncthreads();
    }
    if (threadIdx.x == 0) {
        const float pres = (g_cnt[bc] > 0) ? 1.0f : 0.0f;
        g_part[blockIdx.x] = sred[0] * pres;
    }
}

__global__ void k_final(float* __restrict__ out) {
    __shared__ float sred[512];
    const int i = threadIdx.x;
    sred[i] = g_part[i];
    __syncthreads();
    #pragma unroll
    for (int s = 256; s > 0; s >>= 1) {
        if (i < s) sred[i] += sred[i + s];
        __syncthreads();
    }
    if (i == 0) {
        int n = 0;
        #pragma unroll
        for (int k = 0; k < BB*CC; ++k) n += (g_cnt[k] > 0) ? 1 : 0;
        const float nf = (n > 0) ? (float)n : 1.0f;
        out[0] = sred[0] / nf;
    }
}

// ---------------------------------------------------------------------------
extern "C" void kernel_launch(void* const* d_in, const int* in_sizes, int n_in,
                              void* d_out, int out_size) {
    const float* output = (const float*)d_in[0];   // [4,8,256,256] fp32
    const int*   target = (const int*)d_in[1];     // [4,256,256] int32
    float*       out    = (float*)d_out;           // scalar

    k_init   <<<1, 32>>>();
    k_softmax<<<(BB*HH*WW)/(2*128), 128>>>(output);
    k_rowpass<<<BB*HH, WW>>>(target);
    k_colpass<<<BB*CC*(WW/JT), 256>>>();
    k_final  <<<1, 512>>>(out);
}